// round 8
// baseline (speedup 1.0000x reference)
#include <cuda_runtime.h>

#define NV   16000
#define PPV  32
#define CIN  10
#define NB   16000
#define BH   496
#define BW   432
#define OUTWH (BW*BH)          // 214272
#define OUTSZ (128*OUTWH)      // 27426816

// ---------------- static device scratch (no runtime allocation) ----------------
__device__ __align__(16) float g_voxelwise[NV * 64];   // [Nv][64]
__device__ __align__(16) float g_h2[NB * 512];         // [Nb][16][32]

extern __shared__ float sm_dyn[];

// mish(x) = x * tanh(softplus(x)) = x * t(t+2)/(t(t+2)+2), t = e^x
__device__ __forceinline__ float mishf(float x) {
    float t = __expf(fminf(x, 20.0f));
    float r = t * (t + 2.0f);
    return x * __fdividef(r, r + 2.0f);
}

// packed f32x2 FMA: d = a*b + d (elementwise, rn) — sm_100+ FFMA2
__device__ __forceinline__ void fma2(float2& d, const float2 a, const float2 b) {
    asm("fma.rn.f32x2 %0, %1, %2, %0;"
        : "+l"(reinterpret_cast<unsigned long long&>(d))
        : "l"(reinterpret_cast<const unsigned long long&>(a)),
          "l"(reinterpret_cast<const unsigned long long&>(b)));
}

// named barrier over 128 threads (4 contiguous warps)
__device__ __forceinline__ void barg(int id) {
    asm volatile("bar.sync %0, 128;" :: "r"(id) : "memory");
}

// ============================================================================
// Kernel 0: zero the output map
// ============================================================================
__global__ void zero_kernel(float4* __restrict__ out, int n4) {
    int i = blockIdx.x * blockDim.x + threadIdx.x;
    if (i < n4) out[i] = make_float4(0.f, 0.f, 0.f, 0.f);
}

// ============================================================================
// Kernel 1: VFE (R6 version). block=128, thread=(pgrp:4 points, ogrp:4 outs),
// VPB voxels per block.
// ============================================================================
#define VPB 8
#define A_W1T 0        // [10][68]
#define A_W2T 680      // [64][68]
#define A_W3T 5032
#define A_W4T 9384
#define A_GB  13736    // 4 layers x (gamma64 | beta64)
#define A_XT  14248    // [64][36]
#define A_MSK 16552    // [32]
#define A_SMEM_FLOATS 16584
#define A_SMEM_BYTES  (A_SMEM_FLOATS * 4)

template<int CINT>
__device__ __forceinline__ void fel_layer(
    const float* __restrict__ Wt, const float* __restrict__ gb,
    const float* __restrict__ xT, int p0, int o0, float (&y)[4][4])
{
    float2 acc[2][4];
    #pragma unroll
    for (int pj = 0; pj < 2; pj++)
        #pragma unroll
        for (int oi = 0; oi < 4; oi++) acc[pj][oi] = make_float2(0.f, 0.f);

    #pragma unroll 4
    for (int c = 0; c < CINT; c++) {
        float4 xv = *(const float4*)(xT + c*36 + p0);
        float4 wv = *(const float4*)(Wt + c*68 + o0);
        float2 x01 = make_float2(xv.x, xv.y);
        float2 x23 = make_float2(xv.z, xv.w);
        float2 w0 = make_float2(wv.x, wv.x);
        float2 w1 = make_float2(wv.y, wv.y);
        float2 w2 = make_float2(wv.z, wv.z);
        float2 w3 = make_float2(wv.w, wv.w);
        fma2(acc[0][0], x01, w0);
        fma2(acc[0][1], x01, w1);
        fma2(acc[0][2], x01, w2);
        fma2(acc[0][3], x01, w3);
        fma2(acc[1][0], x23, w0);
        fma2(acc[1][1], x23, w1);
        fma2(acc[1][2], x23, w2);
        fma2(acc[1][3], x23, w3);
    }
    #pragma unroll
    for (int oi = 0; oi < 4; oi++) {
        y[0][oi] = acc[0][oi].x;
        y[1][oi] = acc[0][oi].y;
        y[2][oi] = acc[1][oi].x;
        y[3][oi] = acc[1][oi].y;
    }
    #pragma unroll
    for (int pi = 0; pi < 4; pi++) {
        float s  = y[pi][0] + y[pi][1] + y[pi][2] + y[pi][3];
        float ss = y[pi][0]*y[pi][0] + y[pi][1]*y[pi][1]
                 + y[pi][2]*y[pi][2] + y[pi][3]*y[pi][3];
        #pragma unroll
        for (int off = 8; off >= 1; off >>= 1) {
            s  += __shfl_xor_sync(0xffffffffu, s,  off);
            ss += __shfl_xor_sync(0xffffffffu, ss, off);
        }
        float m = s * (1.f/64.f);
        float r = rsqrtf(ss * (1.f/64.f) - m*m + 1e-5f);
        #pragma unroll
        for (int oi = 0; oi < 4; oi++) {
            float t = (y[pi][oi] - m) * r * gb[o0+oi] + gb[64+o0+oi];
            y[pi][oi] = mishf(t);
        }
    }
}

__global__ void __launch_bounds__(128, 3) vfe_kernel(
    const float* __restrict__ voxels, const float* __restrict__ voxelmask,
    const float* __restrict__ W1, const float* __restrict__ g1, const float* __restrict__ b1,
    const float* __restrict__ W2, const float* __restrict__ g2, const float* __restrict__ b2,
    const float* __restrict__ W3, const float* __restrict__ g3, const float* __restrict__ b3,
    const float* __restrict__ W4, const float* __restrict__ g4, const float* __restrict__ b4)
{
    float* sW1t = sm_dyn + A_W1T;
    float* sW2t = sm_dyn + A_W2T;
    float* sW3t = sm_dyn + A_W3T;
    float* sW4t = sm_dyn + A_W4T;
    float* sGB  = sm_dyn + A_GB;
    float* sXT  = sm_dyn + A_XT;
    float* sMsk = sm_dyn + A_MSK;

    const int tid = threadIdx.x;

    for (int i = tid; i < 64*CIN; i += 128) {
        int o = i / CIN, c = i - o*CIN;
        sW1t[c*68 + o] = W1[i];
    }
    for (int i = tid; i < 64*64; i += 128) {
        int o = i >> 6, c = i & 63;
        sW2t[c*68 + o] = W2[i];
        sW3t[c*68 + o] = W3[i];
        sW4t[c*68 + o] = W4[i];
    }
    if (tid < 64) {
        sGB[      tid] = g1[tid];  sGB[ 64 + tid] = b1[tid];
        sGB[128 + tid] = g2[tid];  sGB[192 + tid] = b2[tid];
        sGB[256 + tid] = g3[tid];  sGB[320 + tid] = b3[tid];
        sGB[384 + tid] = g4[tid];  sGB[448 + tid] = b4[tid];
    }

    const int pgrp = tid >> 4, ogrp = tid & 15;
    const int p0 = pgrp * 4,  o0 = ogrp * 4;

    for (int vb = 0; vb < VPB; vb++) {
        const int v = blockIdx.x * VPB + vb;
        __syncthreads();
        for (int i = tid; i < PPV*CIN; i += 128) {
            int p = i / CIN, c = i - p*CIN;
            sXT[c*36 + p] = voxels[v * (PPV*CIN) + i];
        }
        if (tid < PPV) sMsk[tid] = voxelmask[v*PPV + tid];
        __syncthreads();

        float msk[4];
        #pragma unroll
        for (int pi = 0; pi < 4; pi++) msk[pi] = sMsk[p0 + pi];

        float y[4][4], x2r[4][4];

        fel_layer<CIN>(sW1t, sGB, sXT, p0, o0, y);
        __syncthreads();
        #pragma unroll
        for (int oi = 0; oi < 4; oi++)
            *(float4*)(sXT + (o0+oi)*36 + p0) =
                make_float4(y[0][oi], y[1][oi], y[2][oi], y[3][oi]);
        __syncthreads();

        fel_layer<64>(sW2t, sGB + 128, sXT, p0, o0, y);
        #pragma unroll
        for (int pi = 0; pi < 4; pi++)
            #pragma unroll
            for (int oi = 0; oi < 4; oi++) {
                y[pi][oi] *= msk[pi];
                x2r[pi][oi] = y[pi][oi];
            }
        __syncthreads();
        #pragma unroll
        for (int oi = 0; oi < 4; oi++)
            *(float4*)(sXT + (o0+oi)*36 + p0) =
                make_float4(y[0][oi], y[1][oi], y[2][oi], y[3][oi]);
        __syncthreads();

        fel_layer<64>(sW3t, sGB + 256, sXT, p0, o0, y);
        __syncthreads();
        #pragma unroll
        for (int oi = 0; oi < 4; oi++)
            *(float4*)(sXT + (o0+oi)*36 + p0) =
                make_float4(y[0][oi], y[1][oi], y[2][oi], y[3][oi]);
        __syncthreads();

        fel_layer<64>(sW4t, sGB + 384, sXT, p0, o0, y);
        float mx[4];
        #pragma unroll
        for (int oi = 0; oi < 4; oi++) {
            #pragma unroll
            for (int pi = 0; pi < 4; pi++)
                y[pi][oi] = fmaf(y[pi][oi], msk[pi], x2r[pi][oi]);
            mx[oi] = fmaxf(fmaxf(y[0][oi], y[1][oi]), fmaxf(y[2][oi], y[3][oi]));
        }
        __syncthreads();
        #pragma unroll
        for (int oi = 0; oi < 4; oi++)
            sXT[(o0+oi)*36 + pgrp] = mx[oi];
        __syncthreads();
        if (tid < 64) {
            float m = sXT[tid*36];
            #pragma unroll
            for (int j = 1; j < 8; j++) m = fmaxf(m, sXT[tid*36 + j]);
            g_voxelwise[v*64 + tid] = m;
        }
    }
}

// ============================================================================
// Kernel 2 (REBUILT): bfe1 + bevmask + bfe2a with 2-D register tiling.
// grid=(32,16): blockIdx.y = branch g. block=256 = 32 cells x 8 o-octets.
// Thread computes a 4p x 8o tile; x staged in smem as float4 (p packed).
// W smem traffic cut 8x vs per-channel threading.
// ============================================================================
#define B1_CELLS 32
#define B1_SW   0        // [64v][64o]           4096 floats
#define B1_SX   4096     // float4[32][64]       8192 floats (16KB-aligned)
#define B1_SW2A 12288    // [8][64]              512 floats
#define B1_SG1  12800
#define B1_SB1  12864
#define B1_SG2A 12928
#define B1_SB2A 12936
#define B1_SMSK 12944
#define B1_SMEM_FLOATS 12976
#define B1_SMEM_BYTES  (B1_SMEM_FLOATS * 4)

__global__ void __launch_bounds__(256, 3) bev1_kernel(
    const int*   __restrict__ bevsidx, const float* __restrict__ bevmask,
    const float* __restrict__ W1,  const float* __restrict__ G1,  const float* __restrict__ Bb1,
    const float* __restrict__ W2a, const float* __restrict__ G2a, const float* __restrict__ B2a)
{
    float*  sW   = sm_dyn + B1_SW;
    float4* sX   = (float4*)(sm_dyn + B1_SX);     // [cell][v] / later [cell][c] (y, p packed)
    float*  sW2a = sm_dyn + B1_SW2A;
    float*  sG1  = sm_dyn + B1_SG1;
    float*  sB1  = sm_dyn + B1_SB1;
    float*  sG2a = sm_dyn + B1_SG2A;
    float*  sB2a = sm_dyn + B1_SB2A;
    float*  sMsk = sm_dyn + B1_SMSK;

    const int tid = threadIdx.x;
    const int g = blockIdx.y;

    for (int i = tid; i < 4096; i += 256) {
        int o = i >> 6, v = i & 63;
        sW[v*64 + o] = W1[g*4096 + i];      // store transposed [v][o]
    }
    for (int i = tid; i < 512; i += 256) sW2a[i] = W2a[g*512 + i];
    if (tid < 64) { sG1[tid] = G1[g*64 + tid]; sB1[tid] = Bb1[g*64 + tid]; }
    if (tid < 8)  { sG2a[tid] = G2a[g*8 + tid]; sB2a[tid] = B2a[g*8 + tid]; }

    const int cell = tid >> 3;     // 0..31
    const int o8   = tid & 7;      // output octet

    for (int chunk = blockIdx.x; chunk < NB/B1_CELLS; chunk += gridDim.x) {
        const int n0 = chunk * B1_CELLS;
        __syncthreads();   // protect sX reuse from previous iteration
        #pragma unroll
        for (int j = 0; j < 8; j++) {
            int i = tid + j*256;
            int idx = bevsidx[n0*64 + i];
            sX[i] = *(const float4*)(g_voxelwise + idx*64 + g*4);  // 4 p-channels
        }
        if (tid < B1_CELLS) sMsk[tid] = bevmask[n0 + tid];
        __syncthreads();

        // ---- bfe1 GEMM: 4p x 8o register tile, reduce over v ----
        float2 acc[4][4];   // [p][o-pair]
        #pragma unroll
        for (int p = 0; p < 4; p++)
            #pragma unroll
            for (int j = 0; j < 4; j++) acc[p][j] = make_float2(0.f, 0.f);

        const float4* xr = sX + cell*64;
        const float*  wb = sW + o8*8;
        #pragma unroll 2
        for (int v = 0; v < 64; v++) {
            float4 x  = xr[v];
            float4 w0 = *(const float4*)(wb + v*64);
            float4 w1 = *(const float4*)(wb + v*64 + 4);
            float2 wp0 = make_float2(w0.x, w0.y), wp1 = make_float2(w0.z, w0.w);
            float2 wp2 = make_float2(w1.x, w1.y), wp3 = make_float2(w1.z, w1.w);
            float2 xp;
            xp = make_float2(x.x, x.x);
            fma2(acc[0][0], xp, wp0); fma2(acc[0][1], xp, wp1);
            fma2(acc[0][2], xp, wp2); fma2(acc[0][3], xp, wp3);
            xp = make_float2(x.y, x.y);
            fma2(acc[1][0], xp, wp0); fma2(acc[1][1], xp, wp1);
            fma2(acc[1][2], xp, wp2); fma2(acc[1][3], xp, wp3);
            xp = make_float2(x.z, x.z);
            fma2(acc[2][0], xp, wp0); fma2(acc[2][1], xp, wp1);
            fma2(acc[2][2], xp, wp2); fma2(acc[2][3], xp, wp3);
            xp = make_float2(x.w, x.w);
            fma2(acc[3][0], xp, wp0); fma2(acc[3][1], xp, wp1);
            fma2(acc[3][2], xp, wp2); fma2(acc[3][3], xp, wp3);
        }

        // ---- LN(64) per (cell,p): reduce over the 8 o8 lanes ----
        float m[4], r[4];
        #pragma unroll
        for (int p = 0; p < 4; p++) {
            float s = 0.f, q = 0.f;
            #pragma unroll
            for (int j = 0; j < 4; j++) {
                s += acc[p][j].x + acc[p][j].y;
                q += acc[p][j].x*acc[p][j].x + acc[p][j].y*acc[p][j].y;
            }
            #pragma unroll
            for (int off = 4; off >= 1; off >>= 1) {
                s += __shfl_xor_sync(0xffffffffu, s, off);
                q += __shfl_xor_sync(0xffffffffu, q, off);
            }
            m[p] = s * (1.f/64.f);
            r[p] = rsqrtf(q * (1.f/64.f) - m[p]*m[p] + 1e-5f);
        }
        float mk = sMsk[cell];

        // mish + mask; write y back into sX[cell][c] (p packed in float4).
        // Readers/writers of sX[cell] are the same 8 lanes -> warp-sync only.
        __syncwarp();
        #pragma unroll
        for (int j = 0; j < 4; j++) {
            int c0 = o8*8 + 2*j;
            float4 va, vb;
            va.x = mishf((acc[0][j].x - m[0])*r[0]*sG1[c0] + sB1[c0]) * mk;
            va.y = mishf((acc[1][j].x - m[1])*r[1]*sG1[c0] + sB1[c0]) * mk;
            va.z = mishf((acc[2][j].x - m[2])*r[2]*sG1[c0] + sB1[c0]) * mk;
            va.w = mishf((acc[3][j].x - m[3])*r[3]*sG1[c0] + sB1[c0]) * mk;
            vb.x = mishf((acc[0][j].y - m[0])*r[0]*sG1[c0+1] + sB1[c0+1]) * mk;
            vb.y = mishf((acc[1][j].y - m[1])*r[1]*sG1[c0+1] + sB1[c0+1]) * mk;
            vb.z = mishf((acc[2][j].y - m[2])*r[2]*sG1[c0+1] + sB1[c0+1]) * mk;
            vb.w = mishf((acc[3][j].y - m[3])*r[3]*sG1[c0+1] + sB1[c0+1]) * mk;
            sX[cell*64 + c0]     = va;
            sX[cell*64 + c0 + 1] = vb;
        }
        __syncwarp();

        // ---- bfe2a: z[p] for this thread's o8, reduce over 64 channels ----
        float2 z01 = make_float2(0.f, 0.f), z23 = make_float2(0.f, 0.f);
        const float* w2r = sW2a + o8*64;
        #pragma unroll 8
        for (int c = 0; c < 64; c++) {
            float4 yv = xr[c];
            float w = w2r[c];
            float2 ww = make_float2(w, w);
            fma2(z01, make_float2(yv.x, yv.y), ww);
            fma2(z23, make_float2(yv.z, yv.w), ww);
        }
        float z[4] = { z01.x, z01.y, z23.x, z23.y };

        // LN(8) over o8 lanes, per p; write x17 to g_h2
        const int n = n0 + cell;
        #pragma unroll
        for (int p = 0; p < 4; p++) {
            float s = z[p], q = z[p]*z[p];
            #pragma unroll
            for (int off = 4; off >= 1; off >>= 1) {
                s += __shfl_xor_sync(0xffffffffu, s, off);
                q += __shfl_xor_sync(0xffffffffu, q, off);
            }
            float mm = s * 0.125f;
            float rr = rsqrtf(q * 0.125f - mm*mm + 1e-5f);
            g_h2[n*512 + g*32 + p*8 + o8] =
                mishf((z[p] - mm) * rr * sG2a[o8] + sB2a[o8]);
        }
    }
}

// ============================================================================
// Kernel 3 (R7 version): bfe2b + bfe3(x2) + residual + scatter.
// block=256 = 2 independent quad-halves x 128 threads sharing weight smem.
// ============================================================================
#define B2_SMEM_FLOATS 28224
#define B2_SMEM_BYTES  (B2_SMEM_FLOATS * 4)

__device__ __forceinline__ void block_ln4(
    const float z[4], float* sred, int lane, int warp4, int bar,
    float m[4], float r[4])
{
    float s[4], q[4];
    #pragma unroll
    for (int k = 0; k < 4; k++) { s[k] = z[k]; q[k] = z[k]*z[k]; }
    #pragma unroll
    for (int off = 16; off >= 1; off >>= 1) {
        #pragma unroll
        for (int k = 0; k < 4; k++) {
            s[k] += __shfl_xor_sync(0xffffffffu, s[k], off);
            q[k] += __shfl_xor_sync(0xffffffffu, q[k], off);
        }
    }
    if (lane == 0) {
        #pragma unroll
        for (int k = 0; k < 4; k++) {
            sred[warp4*8 + k]     = s[k];
            sred[warp4*8 + 4 + k] = q[k];
        }
    }
    barg(bar);
    #pragma unroll
    for (int k = 0; k < 4; k++) {
        s[k] = sred[k]   + sred[8+k]  + sred[16+k] + sred[24+k];
        q[k] = sred[4+k] + sred[12+k] + sred[20+k] + sred[28+k];
    }
    barg(bar);
    #pragma unroll
    for (int k = 0; k < 4; k++) {
        m[k] = s[k] * (1.f/128.f);
        r[k] = rsqrtf(q[k] * (1.f/128.f) - m[k]*m[k] + 1e-5f);
    }
}

__global__ void __launch_bounds__(256) bev2_kernel(
    const float* __restrict__ W2b, const float* __restrict__ G2b, const float* __restrict__ B2b,
    const float* __restrict__ W3,  const float* __restrict__ G3,  const float* __restrict__ B3,
    const int*   __restrict__ bevcoors,
    float* __restrict__ out)
{
    const int tid = threadIdx.x;
    const int q = tid >> 7;
    const int t = tid & 127;
    const int bar = q + 1;
    const int lane = t & 31, warp4 = t >> 5;
    const int g = t >> 3;

    float* sW2b = sm_dyn;                     // 128 x 36
    float* sW3  = sm_dyn + 4608;              // 128 x 132
    float* sG2b = sm_dyn + 21504;
    float* sB2b = sm_dyn + 21632;
    float* sG3  = sm_dyn + 21760;
    float* sB3  = sm_dyn + 21888;
    float* sH   = sm_dyn + 22016 + q*2048;
    float* s17  = sm_dyn + 26112 + q*512;
    float* s18  = sm_dyn + 27136 + q*512;
    float* sred = sm_dyn + 28160 + q*32;

    for (int i = tid; i < 128*32; i += 256) {
        int o = i >> 5, c = i & 31;
        sW2b[o*36 + c] = W2b[i];
    }
    for (int i = tid; i < 128*128; i += 256) {
        int o = i >> 7, c = i & 127;
        sW3[o*132 + c] = W3[i];
    }
    if (tid < 128) {
        sG2b[tid] = G2b[tid]; sB2b[tid] = B2b[tid];
        sG3[tid]  = G3[tid];  sB3[tid]  = B3[tid];
    }
    __syncthreads();

    for (int qb = blockIdx.x; qb < NB/8; qb += gridDim.x) {
        const int n0 = qb*8 + q*4;
        barg(bar);
        for (int i = t; i < 2048; i += 128)
            sH[i] = g_h2[n0*512 + i];
        barg(bar);

        float2 a0 = {0.f,0.f}, a1 = {0.f,0.f}, a2 = {0.f,0.f}, a3 = {0.f,0.f};
        {
            const float* wr = sW2b + t*36;
            const float* h0 = sH + g*32;
            #pragma unroll
            for (int c = 0; c < 32; c += 4) {
                float4 w  = *(const float4*)(wr + c);
                float2 wlo = make_float2(w.x, w.y), whi = make_float2(w.z, w.w);
                float4 xa = *(const float4*)(h0 + c);
                float4 xb = *(const float4*)(h0 + 512 + c);
                float4 xc = *(const float4*)(h0 + 1024 + c);
                float4 xd = *(const float4*)(h0 + 1536 + c);
                fma2(a0, make_float2(xa.x, xa.y), wlo);
                fma2(a0, make_float2(xa.z, xa.w), whi);
                fma2(a1, make_float2(xb.x, xb.y), wlo);
                fma2(a1, make_float2(xb.z, xb.w), whi);
                fma2(a2, make_float2(xc.x, xc.y), wlo);
                fma2(a2, make_float2(xc.z, xc.w), whi);
                fma2(a3, make_float2(xd.x, xd.y), wlo);
                fma2(a3, make_float2(xd.z, xd.w), whi);
            }
        }
        float zz[4] = { a0.x + a0.y, a1.x + a1.y, a2.x + a2.y, a3.x + a3.y };

        float x17[4];
        {
            float s[4], qq[4];
            #pragma unroll
            for (int k = 0; k < 4; k++) { s[k] = zz[k]; qq[k] = zz[k]*zz[k]; }
            #pragma unroll
            for (int off = 4; off >= 1; off >>= 1) {
                #pragma unroll
                for (int k = 0; k < 4; k++) {
                    s[k]  += __shfl_xor_sync(0xffffffffu, s[k],  off);
                    qq[k] += __shfl_xor_sync(0xffffffffu, qq[k], off);
                }
            }
            #pragma unroll
            for (int k = 0; k < 4; k++) {
                float mm = s[k] * 0.125f;
                float rr = rsqrtf(qq[k] * 0.125f - mm*mm + 1e-5f);
                x17[k] = mishf((zz[k] - mm) * rr * sG2b[t] + sB2b[t]);
                s17[k*128 + t] = x17[k];
            }
        }
        barg(bar);

        const float* wr3 = sW3 + t*132;

        a0 = make_float2(0.f,0.f); a1 = make_float2(0.f,0.f);
        a2 = make_float2(0.f,0.f); a3 = make_float2(0.f,0.f);
        #pragma unroll 8
        for (int c = 0; c < 128; c += 4) {
            float4 w  = *(const float4*)(wr3 + c);
            float2 wlo = make_float2(w.x, w.y), whi = make_float2(w.z, w.w);
            float4 xa = *(const float4*)(s17 + c);
            float4 xb = *(const float4*)(s17 + 128 + c);
            float4 xc = *(const float4*)(s17 + 256 + c);
            float4 xd = *(const float4*)(s17 + 384 + c);
            fma2(a0, make_float2(xa.x, xa.y), wlo);
            fma2(a0, make_float2(xa.z, xa.w), whi);
            fma2(a1, make_float2(xb.x, xb.y), wlo);
            fma2(a1, make_float2(xb.z, xb.w), whi);
            fma2(a2, make_float2(xc.x, xc.y), wlo);
            fma2(a2, make_float2(xc.z, xc.w), whi);
            fma2(a3, make_float2(xd.x, xd.y), wlo);
            fma2(a3, make_float2(xd.z, xd.w), whi);
        }
        zz[0] = a0.x + a0.y; zz[1] = a1.x + a1.y;
        zz[2] = a2.x + a2.y; zz[3] = a3.x + a3.y;
        {
            float m[4], r[4];
            block_ln4(zz, sred, lane, warp4, bar, m, r);
            #pragma unroll
            for (int k = 0; k < 4; k++)
                s18[k*128 + t] = mishf((zz[k] - m[k]) * r[k] * sG3[t] + sB3[t]);
        }
        barg(bar);

        a0 = make_float2(0.f,0.f); a1 = make_float2(0.f,0.f);
        a2 = make_float2(0.f,0.f); a3 = make_float2(0.f,0.f);
        #pragma unroll 8
        for (int c = 0; c < 128; c += 4) {
            float4 w  = *(const float4*)(wr3 + c);
            float2 wlo = make_float2(w.x, w.y), whi = make_float2(w.z, w.w);
            float4 xa = *(const float4*)(s18 + c);
            float4 xb = *(const float4*)(s18 + 128 + c);
            float4 xc = *(const float4*)(s18 + 256 + c);
            float4 xd = *(const float4*)(s18 + 384 + c);
            fma2(a0, make_float2(xa.x, xa.y), wlo);
            fma2(a0, make_float2(xa.z, xa.w), whi);
            fma2(a1, make_float2(xb.x, xb.y), wlo);
            fma2(a1, make_float2(xb.z, xb.w), whi);
            fma2(a2, make_float2(xc.x, xc.y), wlo);
            fma2(a2, make_float2(xc.z, xc.w), whi);
            fma2(a3, make_float2(xd.x, xd.y), wlo);
            fma2(a3, make_float2(xd.z, xd.w), whi);
        }
        zz[0] = a0.x + a0.y; zz[1] = a1.x + a1.y;
        zz[2] = a2.x + a2.y; zz[3] = a3.x + a3.y;
        {
            float m[4], r[4];
            block_ln4(zz, sred, lane, warp4, bar, m, r);
            #pragma unroll
            for (int k = 0; k < 4; k++) {
                float x19 = mishf((zz[k] - m[k]) * r[k] * sG3[t] + sB3[t]) + x17[k];
                int2 cc = ((const int2*)bevcoors)[n0 + k];
                out[t*OUTWH + cc.y*BH + cc.x] = x19;
            }
        }
    }
}

// ============================================================================
// launch
// ============================================================================
extern "C" void kernel_launch(void* const* d_in, const int* in_sizes, int n_in,
                              void* d_out, int out_size)
{
    (void)in_sizes; (void)n_in; (void)out_size;

    const float* voxels    = (const float*)d_in[0];
    const float* voxelmask = (const float*)d_in[1];
    const int*   bevsidx   = (const int*)d_in[2];
    const int*   bevcoors  = (const int*)d_in[3];
    const float* bevmask   = (const float*)d_in[4];
    float* out = (float*)d_out;

    cudaFuncSetAttribute(vfe_kernel,  cudaFuncAttributeMaxDynamicSharedMemorySize, A_SMEM_BYTES);
    cudaFuncSetAttribute(bev1_kernel, cudaFuncAttributeMaxDynamicSharedMemorySize, B1_SMEM_BYTES);
    cudaFuncSetAttribute(bev2_kernel, cudaFuncAttributeMaxDynamicSharedMemorySize, B2_SMEM_BYTES);

    zero_kernel<<<(OUTSZ/4 + 255)/256, 256>>>((float4*)out, OUTSZ/4);

    vfe_kernel<<<NV/VPB, 128, A_SMEM_BYTES>>>(
        voxels, voxelmask,
        (const float*)d_in[5],  (const float*)d_in[6],  (const float*)d_in[7],
        (const float*)d_in[8],  (const float*)d_in[9],  (const float*)d_in[10],
        (const float*)d_in[11], (const float*)d_in[12], (const float*)d_in[13],
        (const float*)d_in[14], (const float*)d_in[15], (const float*)d_in[16]);

    bev1_kernel<<<dim3(32, 16), 256, B1_SMEM_BYTES>>>(
        bevsidx, bevmask,
        (const float*)d_in[17], (const float*)d_in[18], (const float*)d_in[19],
        (const float*)d_in[20], (const float*)d_in[21], (const float*)d_in[22]);

    bev2_kernel<<<1000, 256, B2_SMEM_BYTES>>>(
        (const float*)d_in[23], (const float*)d_in[24], (const float*)d_in[25],
        (const float*)d_in[26], (const float*)d_in[27], (const float*)d_in[28],
        bevcoors, out);
}

// round 9
// speedup vs baseline: 1.1810x; 1.1810x over previous
#include <cuda_runtime.h>

#define NV   16000
#define PPV  32
#define CIN  10
#define NB   16000
#define BH   496
#define BW   432
#define OUTWH (BW*BH)          // 214272
#define OUTSZ (128*OUTWH)      // 27426816

// ---------------- static device scratch (no runtime allocation) ----------------
__device__ __align__(16) float g_voxelwise[NV * 64];   // [Nv][64]
__device__ __align__(16) float g_h2[NB * 512];         // [Nb][16][32]
__device__ __align__(16) float g_wt[13760];            // transposed VFE weights

// transposed-weight offsets inside g_wt
#define A_W1T 0        // [10][68]
#define A_W2T 680      // [64][68]
#define A_W3T 5032
#define A_W4T 9384

extern __shared__ float sm_dyn[];

// mish(x) = x * tanh(softplus(x)) = x * t(t+2)/(t(t+2)+2), t = e^x
__device__ __forceinline__ float mishf(float x) {
    float t = __expf(fminf(x, 20.0f));
    float r = t * (t + 2.0f);
    return x * __fdividef(r, r + 2.0f);
}

// packed f32x2 FMA: d = a*b + d (elementwise, rn) — sm_100+ FFMA2
__device__ __forceinline__ void fma2(float2& d, const float2 a, const float2 b) {
    asm("fma.rn.f32x2 %0, %1, %2, %0;"
        : "+l"(reinterpret_cast<unsigned long long&>(d))
        : "l"(reinterpret_cast<const unsigned long long&>(a)),
          "l"(reinterpret_cast<const unsigned long long&>(b)));
}

// named barrier over 128 threads (4 contiguous warps)
__device__ __forceinline__ void barg(int id) {
    asm volatile("bar.sync %0, 128;" :: "r"(id) : "memory");
}

// ============================================================================
// Kernel 0a: zero the output map
// ============================================================================
__global__ void zero_kernel(float4* __restrict__ out, int n4) {
    int i = blockIdx.x * blockDim.x + threadIdx.x;
    if (i < n4) out[i] = make_float4(0.f, 0.f, 0.f, 0.f);
}

// ============================================================================
// Kernel 0b: transpose VFE weights into g_wt (padded [c][68] layout)
// ============================================================================
__global__ void prep_kernel(const float* __restrict__ W1, const float* __restrict__ W2,
                            const float* __restrict__ W3, const float* __restrict__ W4)
{
    int i = blockIdx.x * blockDim.x + threadIdx.x;
    if (i < 640) {
        int o = i / CIN, c = i - o*CIN;
        g_wt[A_W1T + c*68 + o] = W1[i];
    }
    if (i < 4096) {
        int o = i >> 6, c = i & 63;
        g_wt[A_W2T + c*68 + o] = W2[i];
        g_wt[A_W3T + c*68 + o] = W3[i];
        g_wt[A_W4T + c*68 + o] = W4[i];
    }
}

// ============================================================================
// Kernel 1: VFE. block=128, thread=(pgrp:4 points, ogrp:4 outs), VPB voxels/block.
// Weights via __ldg from g_wt (L1-resident, 55KB); smem only activations (11.4KB)
// -> 6 blocks/SM (24 warps, was 12).
// ============================================================================
#define VPB 8
#define V_GB  0        // 4 layers x (gamma64 | beta64) = 512
#define V_XT  512      // [64][36] = 2304
#define V_MSK 2816     // [32]
#define V_SMEM_FLOATS 2848
#define V_SMEM_BYTES  (V_SMEM_FLOATS * 4)

template<int CINT>
__device__ __forceinline__ void fel_layer(
    const float* __restrict__ Wt, const float* __restrict__ gb,
    const float* __restrict__ xT, int p0, int o0, float (&y)[4][4])
{
    float2 acc[2][4];
    #pragma unroll
    for (int pj = 0; pj < 2; pj++)
        #pragma unroll
        for (int oi = 0; oi < 4; oi++) acc[pj][oi] = make_float2(0.f, 0.f);

    #pragma unroll 4
    for (int c = 0; c < CINT; c++) {
        float4 xv = *(const float4*)(xT + c*36 + p0);
        float4 wv = __ldg((const float4*)(Wt + c*68 + o0));
        float2 x01 = make_float2(xv.x, xv.y);
        float2 x23 = make_float2(xv.z, xv.w);
        float2 w0 = make_float2(wv.x, wv.x);
        float2 w1 = make_float2(wv.y, wv.y);
        float2 w2 = make_float2(wv.z, wv.z);
        float2 w3 = make_float2(wv.w, wv.w);
        fma2(acc[0][0], x01, w0);
        fma2(acc[0][1], x01, w1);
        fma2(acc[0][2], x01, w2);
        fma2(acc[0][3], x01, w3);
        fma2(acc[1][0], x23, w0);
        fma2(acc[1][1], x23, w1);
        fma2(acc[1][2], x23, w2);
        fma2(acc[1][3], x23, w3);
    }
    #pragma unroll
    for (int oi = 0; oi < 4; oi++) {
        y[0][oi] = acc[0][oi].x;
        y[1][oi] = acc[0][oi].y;
        y[2][oi] = acc[1][oi].x;
        y[3][oi] = acc[1][oi].y;
    }
    #pragma unroll
    for (int pi = 0; pi < 4; pi++) {
        float s  = y[pi][0] + y[pi][1] + y[pi][2] + y[pi][3];
        float ss = y[pi][0]*y[pi][0] + y[pi][1]*y[pi][1]
                 + y[pi][2]*y[pi][2] + y[pi][3]*y[pi][3];
        #pragma unroll
        for (int off = 8; off >= 1; off >>= 1) {
            s  += __shfl_xor_sync(0xffffffffu, s,  off);
            ss += __shfl_xor_sync(0xffffffffu, ss, off);
        }
        float m = s * (1.f/64.f);
        float r = rsqrtf(ss * (1.f/64.f) - m*m + 1e-5f);
        #pragma unroll
        for (int oi = 0; oi < 4; oi++) {
            float t = (y[pi][oi] - m) * r * gb[o0+oi] + gb[64+o0+oi];
            y[pi][oi] = mishf(t);
        }
    }
}

__global__ void __launch_bounds__(128, 6) vfe_kernel(
    const float* __restrict__ voxels, const float* __restrict__ voxelmask,
    const float* __restrict__ g1, const float* __restrict__ b1,
    const float* __restrict__ g2, const float* __restrict__ b2,
    const float* __restrict__ g3, const float* __restrict__ b3,
    const float* __restrict__ g4, const float* __restrict__ b4)
{
    float* sGB  = sm_dyn + V_GB;
    float* sXT  = sm_dyn + V_XT;
    float* sMsk = sm_dyn + V_MSK;

    const int tid = threadIdx.x;

    if (tid < 64) {
        sGB[      tid] = g1[tid];  sGB[ 64 + tid] = b1[tid];
        sGB[128 + tid] = g2[tid];  sGB[192 + tid] = b2[tid];
        sGB[256 + tid] = g3[tid];  sGB[320 + tid] = b3[tid];
        sGB[384 + tid] = g4[tid];  sGB[448 + tid] = b4[tid];
    }

    const float* sW1t = g_wt + A_W1T;
    const float* sW2t = g_wt + A_W2T;
    const float* sW3t = g_wt + A_W3T;
    const float* sW4t = g_wt + A_W4T;

    const int pgrp = tid >> 4, ogrp = tid & 15;
    const int p0 = pgrp * 4,  o0 = ogrp * 4;

    for (int vb = 0; vb < VPB; vb++) {
        const int v = blockIdx.x * VPB + vb;
        __syncthreads();
        for (int i = tid; i < PPV*CIN; i += 128) {
            int p = i / CIN, c = i - p*CIN;
            sXT[c*36 + p] = voxels[v * (PPV*CIN) + i];
        }
        if (tid < PPV) sMsk[tid] = voxelmask[v*PPV + tid];
        __syncthreads();

        float msk[4];
        #pragma unroll
        for (int pi = 0; pi < 4; pi++) msk[pi] = sMsk[p0 + pi];

        float y[4][4], x2r[4][4];

        fel_layer<CIN>(sW1t, sGB, sXT, p0, o0, y);
        __syncthreads();
        #pragma unroll
        for (int oi = 0; oi < 4; oi++)
            *(float4*)(sXT + (o0+oi)*36 + p0) =
                make_float4(y[0][oi], y[1][oi], y[2][oi], y[3][oi]);
        __syncthreads();

        fel_layer<64>(sW2t, sGB + 128, sXT, p0, o0, y);
        #pragma unroll
        for (int pi = 0; pi < 4; pi++)
            #pragma unroll
            for (int oi = 0; oi < 4; oi++) {
                y[pi][oi] *= msk[pi];
                x2r[pi][oi] = y[pi][oi];
            }
        __syncthreads();
        #pragma unroll
        for (int oi = 0; oi < 4; oi++)
            *(float4*)(sXT + (o0+oi)*36 + p0) =
                make_float4(y[0][oi], y[1][oi], y[2][oi], y[3][oi]);
        __syncthreads();

        fel_layer<64>(sW3t, sGB + 256, sXT, p0, o0, y);
        __syncthreads();
        #pragma unroll
        for (int oi = 0; oi < 4; oi++)
            *(float4*)(sXT + (o0+oi)*36 + p0) =
                make_float4(y[0][oi], y[1][oi], y[2][oi], y[3][oi]);
        __syncthreads();

        fel_layer<64>(sW4t, sGB + 384, sXT, p0, o0, y);
        float mx[4];
        #pragma unroll
        for (int oi = 0; oi < 4; oi++) {
            #pragma unroll
            for (int pi = 0; pi < 4; pi++)
                y[pi][oi] = fmaf(y[pi][oi], msk[pi], x2r[pi][oi]);
            mx[oi] = fmaxf(fmaxf(y[0][oi], y[1][oi]), fmaxf(y[2][oi], y[3][oi]));
        }
        __syncthreads();
        #pragma unroll
        for (int oi = 0; oi < 4; oi++)
            sXT[(o0+oi)*36 + pgrp] = mx[oi];
        __syncthreads();
        if (tid < 64) {
            float m = sXT[tid*36];
            #pragma unroll
            for (int j = 1; j < 8; j++) m = fmaxf(m, sXT[tid*36 + j]);
            g_voxelwise[v*64 + tid] = m;
        }
    }
}

// ============================================================================
// Kernel 2: bfe1 + bevmask + bfe2a (exact R6 version — best measured).
// grid=(125,16): blockIdx.y = branch g. block=128 = 32 cells x 4 p-slots.
// ============================================================================
#define B1_CELLS 32

__global__ void __launch_bounds__(128, 4) bev1_kernel(
    const int*   __restrict__ bevsidx, const float* __restrict__ bevmask,
    const float* __restrict__ W1,  const float* __restrict__ G1,  const float* __restrict__ Bb1,
    const float* __restrict__ W2a, const float* __restrict__ G2a, const float* __restrict__ B2a)
{
    __shared__ __align__(16) float sW1t[64*68];   // [v][o] transposed
    __shared__ __align__(16) float sW2a[512];     // [o8][c]
    __shared__ float sG1[64], sB1[64], sG2a[8], sB2a[8];
    __shared__ int   sidx[B1_CELLS*64];
    __shared__ float smask[B1_CELLS];

    const int tid = threadIdx.x;
    const int g = blockIdx.y;

    for (int i = tid; i < 4096; i += 128) {
        int o = i >> 6, v = i & 63;
        sW1t[v*68 + o] = W1[g*4096 + i];
    }
    for (int i = tid; i < 512; i += 128) sW2a[i] = W2a[g*512 + i];
    if (tid < 64) { sG1[tid] = G1[g*64 + tid]; sB1[tid] = Bb1[g*64 + tid]; }
    if (tid < 8)  { sG2a[tid] = G2a[g*8 + tid]; sB2a[tid] = B2a[g*8 + tid]; }

    const int cell = tid >> 2, p = tid & 3;
    const int c = g*4 + p;

    for (int n0 = blockIdx.x * B1_CELLS; n0 < NB; n0 += gridDim.x * B1_CELLS) {
        __syncthreads();
        for (int i = tid; i < B1_CELLS*64; i += 128)
            sidx[i] = bevsidx[n0*64 + i];
        if (tid < B1_CELLS) smask[tid] = bevmask[n0 + tid];
        __syncthreads();

        const int n = n0 + cell;
        const int* myidx = sidx + cell*64;

        float2 y2[32];   // packed output pairs (o, o+1)
        #pragma unroll
        for (int i = 0; i < 32; i++) y2[i] = make_float2(0.f, 0.f);

        float x0 = g_voxelwise[myidx[0]*64 + c];
        float x1 = g_voxelwise[myidx[1]*64 + c];
        #pragma unroll 2
        for (int v = 0; v < 64; v++) {
            float xv = x0;
            x0 = x1;
            if (v + 2 < 64) x1 = g_voxelwise[myidx[v+2]*64 + c];
            float2 xb = make_float2(xv, xv);
            const float* wr = sW1t + v*68;
            #pragma unroll
            for (int o = 0; o < 64; o += 4) {
                float4 w = *(const float4*)(wr + o);
                fma2(y2[(o>>1)  ], xb, make_float2(w.x, w.y));
                fma2(y2[(o>>1)+1], xb, make_float2(w.z, w.w));
            }
        }

        float s = 0.f, ss = 0.f;
        #pragma unroll
        for (int i = 0; i < 32; i++) {
            s  += y2[i].x + y2[i].y;
            ss += y2[i].x*y2[i].x + y2[i].y*y2[i].y;
        }
        float m = s * (1.f/64.f);
        float r = rsqrtf(ss * (1.f/64.f) - m*m + 1e-5f);
        float mk = smask[cell];
        #pragma unroll
        for (int i = 0; i < 32; i++) {
            y2[i].x = mishf((y2[i].x - m) * r * sG1[2*i  ] + sB1[2*i  ]) * mk;
            y2[i].y = mishf((y2[i].y - m) * r * sG1[2*i+1] + sB1[2*i+1]) * mk;
        }

        float z[8];
        float s2 = 0.f, ss2 = 0.f;
        #pragma unroll
        for (int o8 = 0; o8 < 8; o8++) {
            float2 acc = make_float2(0.f, 0.f);
            const float* wr = sW2a + o8*64;
            #pragma unroll
            for (int cc = 0; cc < 64; cc += 4) {
                float4 w = *(const float4*)(wr + cc);
                fma2(acc, y2[(cc>>1)  ], make_float2(w.x, w.y));
                fma2(acc, y2[(cc>>1)+1], make_float2(w.z, w.w));
            }
            float a = acc.x + acc.y;
            z[o8] = a; s2 += a; ss2 += a*a;
        }
        float m2 = s2 * 0.125f;
        float r2 = rsqrtf(ss2 * 0.125f - m2*m2 + 1e-5f);
        float* dst = g_h2 + n*512 + g*32 + p*8;
        #pragma unroll
        for (int o8 = 0; o8 < 8; o8++)
            dst[o8] = mishf((z[o8] - m2) * r2 * sG2a[o8] + sB2a[o8]);
    }
}

// ============================================================================
// Kernel 3: bfe2b + bfe3(x2) + residual + scatter.
// block=256 = 2 independent quad-halves x 128 threads.
// Weights read from gmem via __ldg (L1-resident: W3 64KB, W2b 16KB) —
// smem drops 113KB -> 27KB => 5 blocks/SM (occupancy 2.5x).
// ============================================================================
#define B2_SMEM_FLOATS 6720
#define B2_SMEM_BYTES  (B2_SMEM_FLOATS * 4)

__device__ __forceinline__ void block_ln4(
    const float z[4], float* sred, int lane, int warp4, int bar,
    float m[4], float r[4])
{
    float s[4], q[4];
    #pragma unroll
    for (int k = 0; k < 4; k++) { s[k] = z[k]; q[k] = z[k]*z[k]; }
    #pragma unroll
    for (int off = 16; off >= 1; off >>= 1) {
        #pragma unroll
        for (int k = 0; k < 4; k++) {
            s[k] += __shfl_xor_sync(0xffffffffu, s[k], off);
            q[k] += __shfl_xor_sync(0xffffffffu, q[k], off);
        }
    }
    if (lane == 0) {
        #pragma unroll
        for (int k = 0; k < 4; k++) {
            sred[warp4*8 + k]     = s[k];
            sred[warp4*8 + 4 + k] = q[k];
        }
    }
    barg(bar);
    #pragma unroll
    for (int k = 0; k < 4; k++) {
        s[k] = sred[k]   + sred[8+k]  + sred[16+k] + sred[24+k];
        q[k] = sred[4+k] + sred[12+k] + sred[20+k] + sred[28+k];
    }
    barg(bar);
    #pragma unroll
    for (int k = 0; k < 4; k++) {
        m[k] = s[k] * (1.f/128.f);
        r[k] = rsqrtf(q[k] * (1.f/128.f) - m[k]*m[k] + 1e-5f);
    }
}

__global__ void __launch_bounds__(256) bev2_kernel(
    const float* __restrict__ W2b, const float* __restrict__ G2b, const float* __restrict__ B2b,
    const float* __restrict__ W3,  const float* __restrict__ G3,  const float* __restrict__ B3,
    const int*   __restrict__ bevcoors,
    float* __restrict__ out)
{
    const int tid = threadIdx.x;
    const int q = tid >> 7;
    const int t = tid & 127;
    const int bar = q + 1;
    const int lane = t & 31, warp4 = t >> 5;
    const int g = t >> 3;

    float* sG2b = sm_dyn;        // 128
    float* sB2b = sm_dyn + 128;
    float* sG3  = sm_dyn + 256;
    float* sB3  = sm_dyn + 384;
    float* sH   = sm_dyn + 512  + q*3104;   // 4 cells x 512
    float* s17  = sm_dyn + 2560 + q*3104;   // 4 x 128
    float* s18  = sm_dyn + 3072 + q*3104;   // 4 x 128
    float* sred = sm_dyn + 3584 + q*3104;   // 32

    if (tid < 128) {
        sG2b[tid] = G2b[tid]; sB2b[tid] = B2b[tid];
        sG3[tid]  = G3[tid];  sB3[tid]  = B3[tid];
    }
    __syncthreads();

    const float* wr2b = W2b + t*32;   // L1-resident row
    const float* wr3  = W3  + t*128;  // L1-resident row

    for (int qb = blockIdx.x; qb < NB/8; qb += gridDim.x) {
        const int n0 = qb*8 + q*4;
        barg(bar);
        for (int i = t; i < 2048; i += 128)
            sH[i] = g_h2[n0*512 + i];
        barg(bar);

        // ---- bfe2b: thread (g=t/8, o8=t%8), 4 cells, packed along c ----
        float2 a0 = {0.f,0.f}, a1 = {0.f,0.f}, a2 = {0.f,0.f}, a3 = {0.f,0.f};
        {
            const float* h0 = sH + g*32;
            #pragma unroll
            for (int c = 0; c < 32; c += 4) {
                float4 w  = __ldg((const float4*)(wr2b + c));
                float2 wlo = make_float2(w.x, w.y), whi = make_float2(w.z, w.w);
                float4 xa = *(const float4*)(h0 + c);
                float4 xb = *(const float4*)(h0 + 512 + c);
                float4 xc = *(const float4*)(h0 + 1024 + c);
                float4 xd = *(const float4*)(h0 + 1536 + c);
                fma2(a0, make_float2(xa.x, xa.y), wlo);
                fma2(a0, make_float2(xa.z, xa.w), whi);
                fma2(a1, make_float2(xb.x, xb.y), wlo);
                fma2(a1, make_float2(xb.z, xb.w), whi);
                fma2(a2, make_float2(xc.x, xc.y), wlo);
                fma2(a2, make_float2(xc.z, xc.w), whi);
                fma2(a3, make_float2(xd.x, xd.y), wlo);
                fma2(a3, make_float2(xd.z, xd.w), whi);
            }
        }
        float zz[4] = { a0.x + a0.y, a1.x + a1.y, a2.x + a2.y, a3.x + a3.y };

        // LN over 8 (lane groups of 8) per cell
        float x17[4];
        {
            float s[4], qq[4];
            #pragma unroll
            for (int k = 0; k < 4; k++) { s[k] = zz[k]; qq[k] = zz[k]*zz[k]; }
            #pragma unroll
            for (int off = 4; off >= 1; off >>= 1) {
                #pragma unroll
                for (int k = 0; k < 4; k++) {
                    s[k]  += __shfl_xor_sync(0xffffffffu, s[k],  off);
                    qq[k] += __shfl_xor_sync(0xffffffffu, qq[k], off);
                }
            }
            #pragma unroll
            for (int k = 0; k < 4; k++) {
                float mm = s[k] * 0.125f;
                float rr = rsqrtf(qq[k] * 0.125f - mm*mm + 1e-5f);
                x17[k] = mishf((zz[k] - mm) * rr * sG2b[t] + sB2b[t]);
                s17[k*128 + t] = x17[k];
            }
        }
        barg(bar);

        // ---- bfe3 layer 1 ----
        a0 = make_float2(0.f,0.f); a1 = make_float2(0.f,0.f);
        a2 = make_float2(0.f,0.f); a3 = make_float2(0.f,0.f);
        #pragma unroll 8
        for (int c = 0; c < 128; c += 4) {
            float4 w  = __ldg((const float4*)(wr3 + c));
            float2 wlo = make_float2(w.x, w.y), whi = make_float2(w.z, w.w);
            float4 xa = *(const float4*)(s17 + c);
            float4 xb = *(const float4*)(s17 + 128 + c);
            float4 xc = *(const float4*)(s17 + 256 + c);
            float4 xd = *(const float4*)(s17 + 384 + c);
            fma2(a0, make_float2(xa.x, xa.y), wlo);
            fma2(a0, make_float2(xa.z, xa.w), whi);
            fma2(a1, make_float2(xb.x, xb.y), wlo);
            fma2(a1, make_float2(xb.z, xb.w), whi);
            fma2(a2, make_float2(xc.x, xc.y), wlo);
            fma2(a2, make_float2(xc.z, xc.w), whi);
            fma2(a3, make_float2(xd.x, xd.y), wlo);
            fma2(a3, make_float2(xd.z, xd.w), whi);
        }
        zz[0] = a0.x + a0.y; zz[1] = a1.x + a1.y;
        zz[2] = a2.x + a2.y; zz[3] = a3.x + a3.y;
        {
            float m[4], r[4];
            block_ln4(zz, sred, lane, warp4, bar, m, r);
            #pragma unroll
            for (int k = 0; k < 4; k++)
                s18[k*128 + t] = mishf((zz[k] - m[k]) * r[k] * sG3[t] + sB3[t]);
        }
        barg(bar);

        // ---- bfe3 layer 2 + residual ----
        a0 = make_float2(0.f,0.f); a1 = make_float2(0.f,0.f);
        a2 = make_float2(0.f,0.f); a3 = make_float2(0.f,0.f);
        #pragma unroll 8
        for (int c = 0; c < 128; c += 4) {
            float4 w  = __ldg((const float4*)(wr3 + c));
            float2 wlo = make_float2(w.x, w.y), whi = make_float2(w.z, w.w);
            float4 xa = *(const float4*)(s18 + c);
            float4 xb = *(const float4*)(s18 + 128 + c);
            float4 xc = *(const float4*)(s18 + 256 + c);
            float4 xd = *(const float4*)(s18 + 384 + c);
            fma2(a0, make_float2(xa.x, xa.y), wlo);
            fma2(a0, make_float2(xa.z, xa.w), whi);
            fma2(a1, make_float2(xb.x, xb.y), wlo);
            fma2(a1, make_float2(xb.z, xb.w), whi);
            fma2(a2, make_float2(xc.x, xc.y), wlo);
            fma2(a2, make_float2(xc.z, xc.w), whi);
            fma2(a3, make_float2(xd.x, xd.y), wlo);
            fma2(a3, make_float2(xd.z, xd.w), whi);
        }
        zz[0] = a0.x + a0.y; zz[1] = a1.x + a1.y;
        zz[2] = a2.x + a2.y; zz[3] = a3.x + a3.y;
        {
            float m[4], r[4];
            block_ln4(zz, sred, lane, warp4, bar, m, r);
            #pragma unroll
            for (int k = 0; k < 4; k++) {
                float x19 = mishf((zz[k] - m[k]) * r[k] * sG3[t] + sB3[t]) + x17[k];
                int2 cc = ((const int2*)bevcoors)[n0 + k];
                out[t*OUTWH + cc.y*BH + cc.x] = x19;
            }
        }
    }
}

// ============================================================================
// launch
// ============================================================================
extern "C" void kernel_launch(void* const* d_in, const int* in_sizes, int n_in,
                              void* d_out, int out_size)
{
    (void)in_sizes; (void)n_in; (void)out_size;

    const float* voxels    = (const float*)d_in[0];
    const float* voxelmask = (const float*)d_in[1];
    const int*   bevsidx   = (const int*)d_in[2];
    const int*   bevcoors  = (const int*)d_in[3];
    const float* bevmask   = (const float*)d_in[4];
    float* out = (float*)d_out;

    cudaFuncSetAttribute(vfe_kernel,  cudaFuncAttributeMaxDynamicSharedMemorySize, V_SMEM_BYTES);
    cudaFuncSetAttribute(bev2_kernel, cudaFuncAttributeMaxDynamicSharedMemorySize, B2_SMEM_BYTES);

    zero_kernel<<<(OUTSZ/4 + 255)/256, 256>>>((float4*)out, OUTSZ/4);

    prep_kernel<<<16, 256>>>(
        (const float*)d_in[5], (const float*)d_in[8],
        (const float*)d_in[11], (const float*)d_in[14]);

    vfe_kernel<<<NV/VPB, 128, V_SMEM_BYTES>>>(
        voxels, voxelmask,
        (const float*)d_in[6],  (const float*)d_in[7],
        (const float*)d_in[9],  (const float*)d_in[10],
        (const float*)d_in[12], (const float*)d_in[13],
        (const float*)d_in[15], (const float*)d_in[16]);

    bev1_kernel<<<dim3(125, 16), 128>>>(
        bevsidx, bevmask,
        (const float*)d_in[17], (const float*)d_in[18], (const float*)d_in[19],
        (const float*)d_in[20], (const float*)d_in[21], (const float*)d_in[22]);

    bev2_kernel<<<2000, 256, B2_SMEM_BYTES>>>(
        (const float*)d_in[23], (const float*)d_in[24], (const float*)d_in[25],
        (const float*)d_in[26], (const float*)d_in[27], (const float*)d_in[28],
        bevcoors, out);
}

// round 10
// speedup vs baseline: 1.2515x; 1.0597x over previous
#include <cuda_runtime.h>

#define NV   16000
#define PPV  32
#define CIN  10
#define NB   16000
#define BH   496
#define BW   432
#define OUTWH (BW*BH)          // 214272
#define OUTSZ (128*OUTWH)      // 27426816

// ---------------- static device scratch (no runtime allocation) ----------------
__device__ __align__(16) float g_voxelwise[NV * 64];   // [Nv][64]
__device__ __align__(16) float g_h2[NB * 512];         // [Nb][16][32]

extern __shared__ float sm_dyn[];

// mish(x) = x * tanh(softplus(x)) = x * t(t+2)/(t(t+2)+2), t = e^x
__device__ __forceinline__ float mishf(float x) {
    float t = __expf(fminf(x, 20.0f));
    float r = t * (t + 2.0f);
    return x * __fdividef(r, r + 2.0f);
}

// packed f32x2 FMA: d = a*b + d (elementwise, rn) — sm_100+ FFMA2
__device__ __forceinline__ void fma2(float2& d, const float2 a, const float2 b) {
    asm("fma.rn.f32x2 %0, %1, %2, %0;"
        : "+l"(reinterpret_cast<unsigned long long&>(d))
        : "l"(reinterpret_cast<const unsigned long long&>(a)),
          "l"(reinterpret_cast<const unsigned long long&>(b)));
}

// named barrier over 128 threads (4 contiguous warps)
__device__ __forceinline__ void barg(int id) {
    asm volatile("bar.sync %0, 128;" :: "r"(id) : "memory");
}

// ============================================================================
// Kernel 0: zero the output map
// ============================================================================
__global__ void zero_kernel(float4* __restrict__ out, int n4) {
    int i = blockIdx.x * blockDim.x + threadIdx.x;
    if (i < n4) out[i] = make_float4(0.f, 0.f, 0.f, 0.f);
}

// ============================================================================
// Kernel 1: VFE (R6 version — best measured). block=128,
// thread=(pgrp:4 points, ogrp:4 outs), VPB voxels/block, weights in smem.
// ============================================================================
#define VPB 8
#define A_W1T 0        // [10][68]
#define A_W2T 680      // [64][68]
#define A_W3T 5032
#define A_W4T 9384
#define A_GB  13736    // 4 layers x (gamma64 | beta64)
#define A_XT  14248    // [64][36]
#define A_MSK 16552    // [32]
#define A_SMEM_FLOATS 16584
#define A_SMEM_BYTES  (A_SMEM_FLOATS * 4)

template<int CINT>
__device__ __forceinline__ void fel_layer(
    const float* __restrict__ Wt, const float* __restrict__ gb,
    const float* __restrict__ xT, int p0, int o0, float (&y)[4][4])
{
    float2 acc[2][4];
    #pragma unroll
    for (int pj = 0; pj < 2; pj++)
        #pragma unroll
        for (int oi = 0; oi < 4; oi++) acc[pj][oi] = make_float2(0.f, 0.f);

    #pragma unroll 4
    for (int c = 0; c < CINT; c++) {
        float4 xv = *(const float4*)(xT + c*36 + p0);
        float4 wv = *(const float4*)(Wt + c*68 + o0);
        float2 x01 = make_float2(xv.x, xv.y);
        float2 x23 = make_float2(xv.z, xv.w);
        float2 w0 = make_float2(wv.x, wv.x);
        float2 w1 = make_float2(wv.y, wv.y);
        float2 w2 = make_float2(wv.z, wv.z);
        float2 w3 = make_float2(wv.w, wv.w);
        fma2(acc[0][0], x01, w0);
        fma2(acc[0][1], x01, w1);
        fma2(acc[0][2], x01, w2);
        fma2(acc[0][3], x01, w3);
        fma2(acc[1][0], x23, w0);
        fma2(acc[1][1], x23, w1);
        fma2(acc[1][2], x23, w2);
        fma2(acc[1][3], x23, w3);
    }
    #pragma unroll
    for (int oi = 0; oi < 4; oi++) {
        y[0][oi] = acc[0][oi].x;
        y[1][oi] = acc[0][oi].y;
        y[2][oi] = acc[1][oi].x;
        y[3][oi] = acc[1][oi].y;
    }
    #pragma unroll
    for (int pi = 0; pi < 4; pi++) {
        float s  = y[pi][0] + y[pi][1] + y[pi][2] + y[pi][3];
        float ss = y[pi][0]*y[pi][0] + y[pi][1]*y[pi][1]
                 + y[pi][2]*y[pi][2] + y[pi][3]*y[pi][3];
        #pragma unroll
        for (int off = 8; off >= 1; off >>= 1) {
            s  += __shfl_xor_sync(0xffffffffu, s,  off);
            ss += __shfl_xor_sync(0xffffffffu, ss, off);
        }
        float m = s * (1.f/64.f);
        float r = rsqrtf(ss * (1.f/64.f) - m*m + 1e-5f);
        #pragma unroll
        for (int oi = 0; oi < 4; oi++) {
            float t = (y[pi][oi] - m) * r * gb[o0+oi] + gb[64+o0+oi];
            y[pi][oi] = mishf(t);
        }
    }
}

__global__ void __launch_bounds__(128, 3) vfe_kernel(
    const float* __restrict__ voxels, const float* __restrict__ voxelmask,
    const float* __restrict__ W1, const float* __restrict__ g1, const float* __restrict__ b1,
    const float* __restrict__ W2, const float* __restrict__ g2, const float* __restrict__ b2,
    const float* __restrict__ W3, const float* __restrict__ g3, const float* __restrict__ b3,
    const float* __restrict__ W4, const float* __restrict__ g4, const float* __restrict__ b4)
{
    float* sW1t = sm_dyn + A_W1T;
    float* sW2t = sm_dyn + A_W2T;
    float* sW3t = sm_dyn + A_W3T;
    float* sW4t = sm_dyn + A_W4T;
    float* sGB  = sm_dyn + A_GB;
    float* sXT  = sm_dyn + A_XT;
    float* sMsk = sm_dyn + A_MSK;

    const int tid = threadIdx.x;

    for (int i = tid; i < 64*CIN; i += 128) {
        int o = i / CIN, c = i - o*CIN;
        sW1t[c*68 + o] = W1[i];
    }
    for (int i = tid; i < 64*64; i += 128) {
        int o = i >> 6, c = i & 63;
        sW2t[c*68 + o] = W2[i];
        sW3t[c*68 + o] = W3[i];
        sW4t[c*68 + o] = W4[i];
    }
    if (tid < 64) {
        sGB[      tid] = g1[tid];  sGB[ 64 + tid] = b1[tid];
        sGB[128 + tid] = g2[tid];  sGB[192 + tid] = b2[tid];
        sGB[256 + tid] = g3[tid];  sGB[320 + tid] = b3[tid];
        sGB[384 + tid] = g4[tid];  sGB[448 + tid] = b4[tid];
    }

    const int pgrp = tid >> 4, ogrp = tid & 15;
    const int p0 = pgrp * 4,  o0 = ogrp * 4;

    for (int vb = 0; vb < VPB; vb++) {
        const int v = blockIdx.x * VPB + vb;
        __syncthreads();
        for (int i = tid; i < PPV*CIN; i += 128) {
            int p = i / CIN, c = i - p*CIN;
            sXT[c*36 + p] = voxels[v * (PPV*CIN) + i];
        }
        if (tid < PPV) sMsk[tid] = voxelmask[v*PPV + tid];
        __syncthreads();

        float msk[4];
        #pragma unroll
        for (int pi = 0; pi < 4; pi++) msk[pi] = sMsk[p0 + pi];

        float y[4][4], x2r[4][4];

        fel_layer<CIN>(sW1t, sGB, sXT, p0, o0, y);
        __syncthreads();
        #pragma unroll
        for (int oi = 0; oi < 4; oi++)
            *(float4*)(sXT + (o0+oi)*36 + p0) =
                make_float4(y[0][oi], y[1][oi], y[2][oi], y[3][oi]);
        __syncthreads();

        fel_layer<64>(sW2t, sGB + 128, sXT, p0, o0, y);
        #pragma unroll
        for (int pi = 0; pi < 4; pi++)
            #pragma unroll
            for (int oi = 0; oi < 4; oi++) {
                y[pi][oi] *= msk[pi];
                x2r[pi][oi] = y[pi][oi];
            }
        __syncthreads();
        #pragma unroll
        for (int oi = 0; oi < 4; oi++)
            *(float4*)(sXT + (o0+oi)*36 + p0) =
                make_float4(y[0][oi], y[1][oi], y[2][oi], y[3][oi]);
        __syncthreads();

        fel_layer<64>(sW3t, sGB + 256, sXT, p0, o0, y);
        __syncthreads();
        #pragma unroll
        for (int oi = 0; oi < 4; oi++)
            *(float4*)(sXT + (o0+oi)*36 + p0) =
                make_float4(y[0][oi], y[1][oi], y[2][oi], y[3][oi]);
        __syncthreads();

        fel_layer<64>(sW4t, sGB + 384, sXT, p0, o0, y);
        float mx[4];
        #pragma unroll
        for (int oi = 0; oi < 4; oi++) {
            #pragma unroll
            for (int pi = 0; pi < 4; pi++)
                y[pi][oi] = fmaf(y[pi][oi], msk[pi], x2r[pi][oi]);
            mx[oi] = fmaxf(fmaxf(y[0][oi], y[1][oi]), fmaxf(y[2][oi], y[3][oi]));
        }
        __syncthreads();
        #pragma unroll
        for (int oi = 0; oi < 4; oi++)
            sXT[(o0+oi)*36 + pgrp] = mx[oi];
        __syncthreads();
        if (tid < 64) {
            float m = sXT[tid*36];
            #pragma unroll
            for (int j = 1; j < 8; j++) m = fmaxf(m, sXT[tid*36 + j]);
            g_voxelwise[v*64 + tid] = m;
        }
    }
}

// ============================================================================
// Kernel 2 (NEW): bfe1 + bevmask + bfe2a, o-quarter split.
// grid=(125,16): blockIdx.y = branch g. block=128 = 8 quads(4 cells) x 4p x 4h.
// Thread: 4 cells x 16 outputs (quarter). LDS.128 per v: 4 (was 16) ->
// smem wavefront traffic cut 4x. LN reductions across the 4 h-lanes.
// ============================================================================
__global__ void __launch_bounds__(128, 4) bev1_kernel(
    const int*   __restrict__ bevsidx, const float* __restrict__ bevmask,
    const float* __restrict__ W1,  const float* __restrict__ G1,  const float* __restrict__ Bb1,
    const float* __restrict__ W2a, const float* __restrict__ G2a, const float* __restrict__ B2a)
{
    __shared__ __align__(16) float sW1t[64*68];   // [v][o] transposed (pad 68)
    __shared__ __align__(16) float sW2a[512];     // [o8][c]
    __shared__ float sG1[64], sB1[64], sG2a[8], sB2a[8];
    __shared__ int   sidx[32*64];
    __shared__ float smask[32];

    const int tid = threadIdx.x;
    const int g = blockIdx.y;

    for (int i = tid; i < 4096; i += 128) {
        int o = i >> 6, v = i & 63;
        sW1t[v*68 + o] = W1[g*4096 + i];
    }
    for (int i = tid; i < 512; i += 128) sW2a[i] = W2a[g*512 + i];
    if (tid < 64) { sG1[tid] = G1[g*64 + tid]; sB1[tid] = Bb1[g*64 + tid]; }
    if (tid < 8)  { sG2a[tid] = G2a[g*8 + tid]; sB2a[tid] = B2a[g*8 + tid]; }

    const int h    = tid & 3;          // o-quarter (lane bits 0-1)
    const int p    = (tid >> 2) & 3;   // channel row
    const int quad = tid >> 4;         // 0..7 -> cells quad*4 .. +3
    const int c = g*4 + p;
    const int obase = h*16;

    for (int n0 = blockIdx.x * 32; n0 < NB; n0 += gridDim.x * 32) {
        __syncthreads();   // protect sidx reuse
        for (int i = tid; i < 2048; i += 128)
            sidx[i] = bevsidx[n0*64 + i];
        if (tid < 32) smask[tid] = bevmask[n0 + tid];
        __syncthreads();

        const int cell0 = quad * 4;
        const int* idx0 = sidx + (cell0+0)*64;
        const int* idx1 = sidx + (cell0+1)*64;
        const int* idx2 = sidx + (cell0+2)*64;
        const int* idx3 = sidx + (cell0+3)*64;

        float2 acc[4][8];
        #pragma unroll
        for (int k = 0; k < 4; k++)
            #pragma unroll
            for (int j = 0; j < 8; j++) acc[k][j] = make_float2(0.f, 0.f);

        // 2-deep prefetch per cell
        float xc0 = g_voxelwise[idx0[0]*64 + c], xn0 = g_voxelwise[idx0[1]*64 + c];
        float xc1 = g_voxelwise[idx1[0]*64 + c], xn1 = g_voxelwise[idx1[1]*64 + c];
        float xc2 = g_voxelwise[idx2[0]*64 + c], xn2 = g_voxelwise[idx2[1]*64 + c];
        float xc3 = g_voxelwise[idx3[0]*64 + c], xn3 = g_voxelwise[idx3[1]*64 + c];

        #pragma unroll 2
        for (int v = 0; v < 64; v++) {
            const float* wr = sW1t + v*68 + obase;
            float4 w0 = *(const float4*)(wr);
            float4 w1 = *(const float4*)(wr + 4);
            float4 w2 = *(const float4*)(wr + 8);
            float4 w3 = *(const float4*)(wr + 12);
            float2 wp0 = make_float2(w0.x, w0.y), wp1 = make_float2(w0.z, w0.w);
            float2 wp2 = make_float2(w1.x, w1.y), wp3 = make_float2(w1.z, w1.w);
            float2 wp4 = make_float2(w2.x, w2.y), wp5 = make_float2(w2.z, w2.w);
            float2 wp6 = make_float2(w3.x, w3.y), wp7 = make_float2(w3.z, w3.w);

            float2 xb;
            xb = make_float2(xc0, xc0);
            fma2(acc[0][0], xb, wp0); fma2(acc[0][1], xb, wp1);
            fma2(acc[0][2], xb, wp2); fma2(acc[0][3], xb, wp3);
            fma2(acc[0][4], xb, wp4); fma2(acc[0][5], xb, wp5);
            fma2(acc[0][6], xb, wp6); fma2(acc[0][7], xb, wp7);
            xb = make_float2(xc1, xc1);
            fma2(acc[1][0], xb, wp0); fma2(acc[1][1], xb, wp1);
            fma2(acc[1][2], xb, wp2); fma2(acc[1][3], xb, wp3);
            fma2(acc[1][4], xb, wp4); fma2(acc[1][5], xb, wp5);
            fma2(acc[1][6], xb, wp6); fma2(acc[1][7], xb, wp7);
            xb = make_float2(xc2, xc2);
            fma2(acc[2][0], xb, wp0); fma2(acc[2][1], xb, wp1);
            fma2(acc[2][2], xb, wp2); fma2(acc[2][3], xb, wp3);
            fma2(acc[2][4], xb, wp4); fma2(acc[2][5], xb, wp5);
            fma2(acc[2][6], xb, wp6); fma2(acc[2][7], xb, wp7);
            xb = make_float2(xc3, xc3);
            fma2(acc[3][0], xb, wp0); fma2(acc[3][1], xb, wp1);
            fma2(acc[3][2], xb, wp2); fma2(acc[3][3], xb, wp3);
            fma2(acc[3][4], xb, wp4); fma2(acc[3][5], xb, wp5);
            fma2(acc[3][6], xb, wp6); fma2(acc[3][7], xb, wp7);

            xc0 = xn0; xc1 = xn1; xc2 = xn2; xc3 = xn3;
            if (v + 2 < 64) {
                xn0 = g_voxelwise[idx0[v+2]*64 + c];
                xn1 = g_voxelwise[idx1[v+2]*64 + c];
                xn2 = g_voxelwise[idx2[v+2]*64 + c];
                xn3 = g_voxelwise[idx3[v+2]*64 + c];
            }
        }

        // ---- LN(64) per (cell,p): combine across 4 h-lanes ----
        float m[4], r[4], mk[4];
        #pragma unroll
        for (int k = 0; k < 4; k++) {
            float s = 0.f, ss = 0.f;
            #pragma unroll
            for (int j = 0; j < 8; j++) {
                s  += acc[k][j].x + acc[k][j].y;
                ss += acc[k][j].x*acc[k][j].x + acc[k][j].y*acc[k][j].y;
            }
            s  += __shfl_xor_sync(0xffffffffu, s,  1);
            ss += __shfl_xor_sync(0xffffffffu, ss, 1);
            s  += __shfl_xor_sync(0xffffffffu, s,  2);
            ss += __shfl_xor_sync(0xffffffffu, ss, 2);
            m[k] = s * (1.f/64.f);
            r[k] = rsqrtf(ss * (1.f/64.f) - m[k]*m[k] + 1e-5f);
            mk[k] = smask[cell0 + k];
        }

        // mish + mask (in place)
        #pragma unroll
        for (int k = 0; k < 4; k++) {
            #pragma unroll
            for (int j = 0; j < 8; j++) {
                int cc = obase + 2*j;
                acc[k][j].x = mishf((acc[k][j].x - m[k])*r[k]*sG1[cc  ] + sB1[cc  ]) * mk[k];
                acc[k][j].y = mishf((acc[k][j].y - m[k])*r[k]*sG1[cc+1] + sB1[cc+1]) * mk[k];
            }
        }

        // ---- bfe2a: per-o8 partials from my c-quarter, combined via shuffles;
        //      LN(8) stats accumulated on the fly ----
        float zm[4][2];
        float s2[4], q2[4];
        #pragma unroll
        for (int k = 0; k < 4; k++) { s2[k] = 0.f; q2[k] = 0.f; }

        #pragma unroll
        for (int o8 = 0; o8 < 8; o8++) {
            const float* wr2 = sW2a + o8*64 + obase;
            float4 u0 = *(const float4*)(wr2);
            float4 u1 = *(const float4*)(wr2 + 4);
            float4 u2 = *(const float4*)(wr2 + 8);
            float4 u3 = *(const float4*)(wr2 + 12);
            float2 vp0 = make_float2(u0.x, u0.y), vp1 = make_float2(u0.z, u0.w);
            float2 vp2 = make_float2(u1.x, u1.y), vp3 = make_float2(u1.z, u1.w);
            float2 vp4 = make_float2(u2.x, u2.y), vp5 = make_float2(u2.z, u2.w);
            float2 vp6 = make_float2(u3.x, u3.y), vp7 = make_float2(u3.z, u3.w);
            #pragma unroll
            for (int k = 0; k < 4; k++) {
                float2 a = make_float2(0.f, 0.f);
                fma2(a, acc[k][0], vp0); fma2(a, acc[k][1], vp1);
                fma2(a, acc[k][2], vp2); fma2(a, acc[k][3], vp3);
                fma2(a, acc[k][4], vp4); fma2(a, acc[k][5], vp5);
                fma2(a, acc[k][6], vp6); fma2(a, acc[k][7], vp7);
                float t = a.x + a.y;
                t += __shfl_xor_sync(0xffffffffu, t, 1);
                t += __shfl_xor_sync(0xffffffffu, t, 2);
                s2[k] += t; q2[k] += t*t;
                if ((o8 >> 1) == h) zm[k][o8 & 1] = t;
            }
        }

        #pragma unroll
        for (int k = 0; k < 4; k++) {
            float m2 = s2[k] * 0.125f;
            float r2 = rsqrtf(q2[k] * 0.125f - m2*m2 + 1e-5f);
            float* dst = g_h2 + (n0 + cell0 + k)*512 + g*32 + p*8;
            int oA = h*2, oB = h*2 + 1;
            dst[oA] = mishf((zm[k][0] - m2) * r2 * sG2a[oA] + sB2a[oA]);
            dst[oB] = mishf((zm[k][1] - m2) * r2 * sG2a[oB] + sB2a[oB]);
        }
    }
}

// ============================================================================
// Kernel 3: bfe2b + bfe3(x2) + residual + scatter (R7 version, measured 142us).
// block=256 = 2 independent quad-halves x 128 threads sharing weight smem.
// ============================================================================
#define B2_SMEM_FLOATS 28224
#define B2_SMEM_BYTES  (B2_SMEM_FLOATS * 4)

__device__ __forceinline__ void block_ln4(
    const float z[4], float* sred, int lane, int warp4, int bar,
    float m[4], float r[4])
{
    float s[4], q[4];
    #pragma unroll
    for (int k = 0; k < 4; k++) { s[k] = z[k]; q[k] = z[k]*z[k]; }
    #pragma unroll
    for (int off = 16; off >= 1; off >>= 1) {
        #pragma unroll
        for (int k = 0; k < 4; k++) {
            s[k] += __shfl_xor_sync(0xffffffffu, s[k], off);
            q[k] += __shfl_xor_sync(0xffffffffu, q[k], off);
        }
    }
    if (lane == 0) {
        #pragma unroll
        for (int k = 0; k < 4; k++) {
            sred[warp4*8 + k]     = s[k];
            sred[warp4*8 + 4 + k] = q[k];
        }
    }
    barg(bar);
    #pragma unroll
    for (int k = 0; k < 4; k++) {
        s[k] = sred[k]   + sred[8+k]  + sred[16+k] + sred[24+k];
        q[k] = sred[4+k] + sred[12+k] + sred[20+k] + sred[28+k];
    }
    barg(bar);
    #pragma unroll
    for (int k = 0; k < 4; k++) {
        m[k] = s[k] * (1.f/128.f);
        r[k] = rsqrtf(q[k] * (1.f/128.f) - m[k]*m[k] + 1e-5f);
    }
}

__global__ void __launch_bounds__(256) bev2_kernel(
    const float* __restrict__ W2b, const float* __restrict__ G2b, const float* __restrict__ B2b,
    const float* __restrict__ W3,  const float* __restrict__ G3,  const float* __restrict__ B3,
    const int*   __restrict__ bevcoors,
    float* __restrict__ out)
{
    const int tid = threadIdx.x;
    const int q = tid >> 7;
    const int t = tid & 127;
    const int bar = q + 1;
    const int lane = t & 31, warp4 = t >> 5;
    const int g = t >> 3;

    float* sW2b = sm_dyn;                     // 128 x 36
    float* sW3  = sm_dyn + 4608;              // 128 x 132
    float* sG2b = sm_dyn + 21504;
    float* sB2b = sm_dyn + 21632;
    float* sG3  = sm_dyn + 21760;
    float* sB3  = sm_dyn + 21888;
    float* sH   = sm_dyn + 22016 + q*2048;
    float* s17  = sm_dyn + 26112 + q*512;
    float* s18  = sm_dyn + 27136 + q*512;
    float* sred = sm_dyn + 28160 + q*32;

    for (int i = tid; i < 128*32; i += 256) {
        int o = i >> 5, c = i & 31;
        sW2b[o*36 + c] = W2b[i];
    }
    for (int i = tid; i < 128*128; i += 256) {
        int o = i >> 7, c = i & 127;
        sW3[o*132 + c] = W3[i];
    }
    if (tid < 128) {
        sG2b[tid] = G2b[tid]; sB2b[tid] = B2b[tid];
        sG3[tid]  = G3[tid];  sB3[tid]  = B3[tid];
    }
    __syncthreads();

    for (int qb = blockIdx.x; qb < NB/8; qb += gridDim.x) {
        const int n0 = qb*8 + q*4;
        barg(bar);
        for (int i = t; i < 2048; i += 128)
            sH[i] = g_h2[n0*512 + i];
        barg(bar);

        float2 a0 = {0.f,0.f}, a1 = {0.f,0.f}, a2 = {0.f,0.f}, a3 = {0.f,0.f};
        {
            const float* wr = sW2b + t*36;
            const float* h0 = sH + g*32;
            #pragma unroll
            for (int c = 0; c < 32; c += 4) {
                float4 w  = *(const float4*)(wr + c);
                float2 wlo = make_float2(w.x, w.y), whi = make_float2(w.z, w.w);
                float4 xa = *(const float4*)(h0 + c);
                float4 xb = *(const float4*)(h0 + 512 + c);
                float4 xc = *(const float4*)(h0 + 1024 + c);
                float4 xd = *(const float4*)(h0 + 1536 + c);
                fma2(a0, make_float2(xa.x, xa.y), wlo);
                fma2(a0, make_float2(xa.z, xa.w), whi);
                fma2(a1, make_float2(xb.x, xb.y), wlo);
                fma2(a1, make_float2(xb.z, xb.w), whi);
                fma2(a2, make_float2(xc.x, xc.y), wlo);
                fma2(a2, make_float2(xc.z, xc.w), whi);
                fma2(a3, make_float2(xd.x, xd.y), wlo);
                fma2(a3, make_float2(xd.z, xd.w), whi);
            }
        }
        float zz[4] = { a0.x + a0.y, a1.x + a1.y, a2.x + a2.y, a3.x + a3.y };

        float x17[4];
        {
            float s[4], qq[4];
            #pragma unroll
            for (int k = 0; k < 4; k++) { s[k] = zz[k]; qq[k] = zz[k]*zz[k]; }
            #pragma unroll
            for (int off = 4; off >= 1; off >>= 1) {
                #pragma unroll
                for (int k = 0; k < 4; k++) {
                    s[k]  += __shfl_xor_sync(0xffffffffu, s[k],  off);
                    qq[k] += __shfl_xor_sync(0xffffffffu, qq[k], off);
                }
            }
            #pragma unroll
            for (int k = 0; k < 4; k++) {
                float mm = s[k] * 0.125f;
                float rr = rsqrtf(qq[k] * 0.125f - mm*mm + 1e-5f);
                x17[k] = mishf((zz[k] - mm) * rr * sG2b[t] + sB2b[t]);
                s17[k*128 + t] = x17[k];
            }
        }
        barg(bar);

        const float* wr3 = sW3 + t*132;

        a0 = make_float2(0.f,0.f); a1 = make_float2(0.f,0.f);
        a2 = make_float2(0.f,0.f); a3 = make_float2(0.f,0.f);
        #pragma unroll 8
        for (int c = 0; c < 128; c += 4) {
            float4 w  = *(const float4*)(wr3 + c);
            float2 wlo = make_float2(w.x, w.y), whi = make_float2(w.z, w.w);
            float4 xa = *(const float4*)(s17 + c);
            float4 xb = *(const float4*)(s17 + 128 + c);
            float4 xc = *(const float4*)(s17 + 256 + c);
            float4 xd = *(const float4*)(s17 + 384 + c);
            fma2(a0, make_float2(xa.x, xa.y), wlo);
            fma2(a0, make_float2(xa.z, xa.w), whi);
            fma2(a1, make_float2(xb.x, xb.y), wlo);
            fma2(a1, make_float2(xb.z, xb.w), whi);
            fma2(a2, make_float2(xc.x, xc.y), wlo);
            fma2(a2, make_float2(xc.z, xc.w), whi);
            fma2(a3, make_float2(xd.x, xd.y), wlo);
            fma2(a3, make_float2(xd.z, xd.w), whi);
        }
        zz[0] = a0.x + a0.y; zz[1] = a1.x + a1.y;
        zz[2] = a2.x + a2.y; zz[3] = a3.x + a3.y;
        {
            float m[4], r[4];
            block_ln4(zz, sred, lane, warp4, bar, m, r);
            #pragma unroll
            for (int k = 0; k < 4; k++)
                s18[k*128 + t] = mishf((zz[k] - m[k]) * r[k] * sG3[t] + sB3[t]);
        }
        barg(bar);

        a0 = make_float2(0.f,0.f); a1 = make_float2(0.f,0.f);
        a2 = make_float2(0.f,0.f); a3 = make_float2(0.f,0.f);
        #pragma unroll 8
        for (int c = 0; c < 128; c += 4) {
            float4 w  = *(const float4*)(wr3 + c);
            float2 wlo = make_float2(w.x, w.y), whi = make_float2(w.z, w.w);
            float4 xa = *(const float4*)(s18 + c);
            float4 xb = *(const float4*)(s18 + 128 + c);
            float4 xc = *(const float4*)(s18 + 256 + c);
            float4 xd = *(const float4*)(s18 + 384 + c);
            fma2(a0, make_float2(xa.x, xa.y), wlo);
            fma2(a0, make_float2(xa.z, xa.w), whi);
            fma2(a1, make_float2(xb.x, xb.y), wlo);
            fma2(a1, make_float2(xb.z, xb.w), whi);
            fma2(a2, make_float2(xc.x, xc.y), wlo);
            fma2(a2, make_float2(xc.z, xc.w), whi);
            fma2(a3, make_float2(xd.x, xd.y), wlo);
            fma2(a3, make_float2(xd.z, xd.w), whi);
        }
        zz[0] = a0.x + a0.y; zz[1] = a1.x + a1.y;
        zz[2] = a2.x + a2.y; zz[3] = a3.x + a3.y;
        {
            float m[4], r[4];
            block_ln4(zz, sred, lane, warp4, bar, m, r);
            #pragma unroll
            for (int k = 0; k < 4; k++) {
                float x19 = mishf((zz[k] - m[k]) * r[k] * sG3[t] + sB3[t]) + x17[k];
                int2 cc = ((const int2*)bevcoors)[n0 + k];
                out[t*OUTWH + cc.y*BH + cc.x] = x19;
            }
        }
    }
}

// ============================================================================
// launch
// ============================================================================
extern "C" void kernel_launch(void* const* d_in, const int* in_sizes, int n_in,
                              void* d_out, int out_size)
{
    (void)in_sizes; (void)n_in; (void)out_size;

    const float* voxels    = (const float*)d_in[0];
    const float* voxelmask = (const float*)d_in[1];
    const int*   bevsidx   = (const int*)d_in[2];
    const int*   bevcoors  = (const int*)d_in[3];
    const float* bevmask   = (const float*)d_in[4];
    float* out = (float*)d_out;

    cudaFuncSetAttribute(vfe_kernel,  cudaFuncAttributeMaxDynamicSharedMemorySize, A_SMEM_BYTES);
    cudaFuncSetAttribute(bev2_kernel, cudaFuncAttributeMaxDynamicSharedMemorySize, B2_SMEM_BYTES);

    zero_kernel<<<(OUTSZ/4 + 255)/256, 256>>>((float4*)out, OUTSZ/4);

    vfe_kernel<<<NV/VPB, 128, A_SMEM_BYTES>>>(
        voxels, voxelmask,
        (const float*)d_in[5],  (const float*)d_in[6],  (const float*)d_in[7],
        (const float*)d_in[8],  (const float*)d_in[9],  (const float*)d_in[10],
        (const float*)d_in[11], (const float*)d_in[12], (const float*)d_in[13],
        (const float*)d_in[14], (const float*)d_in[15], (const float*)d_in[16]);

    bev1_kernel<<<dim3(125, 16), 128>>>(
        bevsidx, bevmask,
        (const float*)d_in[17], (const float*)d_in[18], (const float*)d_in[19],
        (const float*)d_in[20], (const float*)d_in[21], (const float*)d_in[22]);

    bev2_kernel<<<1000, 256, B2_SMEM_BYTES>>>(
        (const float*)d_in[23], (const float*)d_in[24], (const float*)d_in[25],
        (const float*)d_in[26], (const float*)d_in[27], (const float*)d_in[28],
        bevcoors, out);
}